// round 16
// baseline (speedup 1.0000x reference)
#include <cuda_runtime.h>
#include <cuda_fp16.h>
#include <cstdint>

// Problem constants
#define BATCH 2
#define L_SEQ 2048
#define CDIM  1024
#define HEADS 16
#define HD    64
#define MTOT  4096
#define THREEC 3072
#define INV4  0.3535533905932738f   // 64^-0.25

// ---------------------------------------------------------------------------
// Scratch (device globals; no allocation allowed)
// ---------------------------------------------------------------------------
__device__ __align__(16) float    g_qkv [(size_t)MTOT * THREEC];  // f32 QKV out
__device__ __align__(16) uint32_t g_qh  [(size_t)MTOT * 512];     // q half perm16 [B,H,L]
__device__ __align__(16) uint32_t g_kh  [(size_t)MTOT * 512];     // k half perm16 [B,H,L]
__device__ __align__(16) uint32_t g_vh  [(size_t)MTOT * 512];     // v half natural [B,H,L][d2]
__device__ __align__(16) uint32_t g_vt  [(size_t)MTOT * 512];     // v^T half [B,H][d][key2 perm16]
__device__ __align__(16) uint32_t g_xh  [(size_t)MTOT * 512];     // x half perm16
__device__ __align__(16) uint32_t g_wh  [(size_t)THREEC * 512];   // w_qkv^T half perm16
__device__ __align__(16) uint32_t g_worh[(size_t)CDIM * 512];     // w_out^T half perm16
__device__ __align__(16) uint32_t g_atth[(size_t)MTOT * 512];     // attn out half perm16

// ---------------------------------------------------------------------------
// Helpers
// ---------------------------------------------------------------------------
__device__ __forceinline__ int p16(int c) { return ((c & 3) << 2) | (c >> 2); }

__device__ __forceinline__ uint32_t pack_h2(float a, float b) {
    __half2 h = __floats2half2_rn(a, b);     // low = a, high = b
    return *reinterpret_cast<uint32_t*>(&h);
}

__device__ __forceinline__ void mma_h(float* d,
                                      uint32_t a0, uint32_t a1, uint32_t a2, uint32_t a3,
                                      uint32_t b0, uint32_t b1) {
    asm volatile(
        "mma.sync.aligned.m16n8k16.row.col.f32.f16.f16.f32 "
        "{%0,%1,%2,%3}, {%4,%5,%6,%7}, {%8,%9}, {%0,%1,%2,%3};\n"
        : "+f"(d[0]), "+f"(d[1]), "+f"(d[2]), "+f"(d[3])
        : "r"(a0), "r"(a1), "r"(a2), "r"(a3), "r"(b0), "r"(b1));
}

__device__ __forceinline__ void cp16(void* smem, const void* gmem) {
    uint32_t s = (uint32_t)__cvta_generic_to_shared(smem);
    asm volatile("cp.async.ca.shared.global [%0], [%1], 16;" :: "r"(s), "l"(gmem));
}
__device__ __forceinline__ void cp_commit() { asm volatile("cp.async.commit_group;"); }
__device__ __forceinline__ void cp_wait0()  { asm volatile("cp.async.wait_group 0;"); }

// ---------------------------------------------------------------------------
// Prep: f32 [R][1024] -> half u32 [R][512] with perm16 along K (validated)
// ---------------------------------------------------------------------------
__global__ __launch_bounds__(256) void cvt_perm_kernel(
    const float* __restrict__ src, uint32_t* __restrict__ dst, int n_f4)
{
    int i = blockIdx.x * blockDim.x + threadIdx.x;
    if (i >= n_f4) return;
    float4 v = ((const float4*)src)[i];
    int row = i >> 8;
    int f4  = i & 255;
    int k2a = 2 * f4, k2b = 2 * f4 + 1;
    int base = row * 512;
    dst[base + (k2a & ~15) + p16(k2a & 15)] = pack_h2(v.x, v.y);
    dst[base + (k2b & ~15) + p16(k2b & 15)] = pack_h2(v.z, v.w);
}

// f32 [K][C] -> half u32 [C][K/2] (transposed) with perm16 along K (validated)
__global__ __launch_bounds__(256) void transpose_cvt_perm_kernel(
    const float* __restrict__ src, uint32_t* __restrict__ dst, int K, int C)
{
    __shared__ float tile[32][33];
    const int c0 = blockIdx.x * 32, k0 = blockIdx.y * 32;
    const int tx = threadIdx.x & 31;
    const int ty = threadIdx.x >> 5;
#pragma unroll
    for (int j = 0; j < 4; j++)
        tile[ty + j * 8][tx] = src[(size_t)(k0 + ty + j * 8) * C + c0 + tx];
    __syncthreads();
#pragma unroll
    for (int j = 0; j < 2; j++) {
        int k2l = ty + 8 * j;
        uint32_t h = pack_h2(tile[2 * k2l][tx], tile[2 * k2l + 1][tx]);
        dst[(size_t)(c0 + tx) * (K / 2) + (k0 >> 1) + p16(k2l)] = h;
    }
}

// ---------------------------------------------------------------------------
// V transpose: vh [bh][L][32 u32] -> vt [bh][64 d][L/2 u32] perm16 (validated)
// ---------------------------------------------------------------------------
__global__ __launch_bounds__(256) void transpose_v_kernel(
    const uint32_t* __restrict__ vh, uint32_t* __restrict__ vt)
{
    __shared__ uint32_t tile[64][33];
    const int bh = blockIdx.y;
    const int t0 = blockIdx.x * 64;
    const int tid = threadIdx.x;

    const uint32_t* src = vh + (size_t)bh * L_SEQ * 32 + (size_t)t0 * 32;
#pragma unroll
    for (int i = 0; i < 8; i++) {
        int idx = tid + i * 256;
        int tok = idx >> 5;
        int d2  = idx & 31;
        tile[tok][d2] = src[tok * 32 + d2];
    }
    __syncthreads();

    uint32_t* dst = vt + (size_t)bh * 64 * (L_SEQ / 2) + (t0 >> 1);
#pragma unroll
    for (int i = 0; i < 8; i++) {
        int idx = tid + i * 256;
        int d   = idx >> 5;
        int k2l = idx & 31;
        uint32_t w0 = tile[2 * k2l][d >> 1];
        uint32_t w1 = tile[2 * k2l + 1][d >> 1];
        uint32_t lo = (d & 1) ? (w0 >> 16) : (w0 & 0xFFFFu);
        uint32_t hi = (d & 1) ? (w1 & 0xFFFF0000u) : (w1 << 16);
        int pos = (k2l & 16) | p16(k2l & 15);
        dst[(size_t)d * (L_SEQ / 2) + pos] = lo | hi;
    }
}

// ---------------------------------------------------------------------------
// fp16 GEMM, 2-stage cp.async double-buffered (R14 verbatim).
// ---------------------------------------------------------------------------
#define GSG 48
#define STAGE_U32 (128 * GSG)
#define GEMM_SMEM_BYTES (4 * STAGE_U32 * 4)

__global__ __launch_bounds__(256, 2) void gemm_h_kernel(
    const uint32_t* __restrict__ A, const uint32_t* __restrict__ Bt,
    float* __restrict__ C, int M, int N)
{
    extern __shared__ uint32_t us[];
    uint32_t* As = us;                    // [2][128][48]
    uint32_t* Bs = us + 2 * STAGE_U32;    // [2][128][48]

    const int tid  = threadIdx.x;
    const int w    = tid >> 5;
    const int lane = tid & 31;
    const int g = lane >> 2;
    const int t = lane & 3;
    const int m0 = blockIdx.y * 128;
    const int n0 = blockIdx.x * 128;
    const int wm = (w & 3) * 32;
    const int wn = (w >> 2) * 64;
    const int K2 = 512;

    const int cp_r0 = tid >> 3;
    const int cp_c4 = (tid & 7) * 4;

    float acc[2][8][4];
#pragma unroll
    for (int mg = 0; mg < 2; mg++)
#pragma unroll
        for (int nn = 0; nn < 8; nn++)
#pragma unroll
            for (int v = 0; v < 4; v++) acc[mg][nn][v] = 0.f;

    {
#pragma unroll
        for (int i = 0; i < 4; i++) {
            int rr = cp_r0 + i * 32;
            cp16(&As[rr * GSG + cp_c4], &A[(size_t)(m0 + rr) * K2 + cp_c4]);
            cp16(&Bs[rr * GSG + cp_c4], &Bt[(size_t)(n0 + rr) * K2 + cp_c4]);
        }
        cp_commit();
    }

    int buf = 0;
    for (int k0 = 0; k0 < K2; k0 += 32) {
        cp_wait0();
        __syncthreads();

        if (k0 + 32 < K2) {
            const int nb = buf ^ 1;
#pragma unroll
            for (int i = 0; i < 4; i++) {
                int rr = cp_r0 + i * 32;
                cp16(&As[nb * STAGE_U32 + rr * GSG + cp_c4],
                     &A[(size_t)(m0 + rr) * K2 + k0 + 32 + cp_c4]);
                cp16(&Bs[nb * STAGE_U32 + rr * GSG + cp_c4],
                     &Bt[(size_t)(n0 + rr) * K2 + k0 + 32 + cp_c4]);
            }
            cp_commit();
        }

        const uint32_t* as = &As[buf * STAGE_U32];
        const uint32_t* bs = &Bs[buf * STAGE_U32];
#pragma unroll
        for (int kp = 0; kp < 2; kp++) {
            uint4 Ag[2][2];
#pragma unroll
            for (int mg = 0; mg < 2; mg++) {
                Ag[mg][0] = *(const uint4*)&as[(wm + mg * 16 + g)     * GSG + kp * 16 + 4 * t];
                Ag[mg][1] = *(const uint4*)&as[(wm + mg * 16 + g + 8) * GSG + kp * 16 + 4 * t];
            }
#pragma unroll
            for (int nn = 0; nn < 8; nn++) {
                uint4 Bv = *(const uint4*)&bs[(wn + nn * 8 + g) * GSG + kp * 16 + 4 * t];
#pragma unroll
                for (int mg = 0; mg < 2; mg++) {
                    mma_h(acc[mg][nn], Ag[mg][0].x, Ag[mg][1].x, Ag[mg][0].y, Ag[mg][1].y,
                          Bv.x, Bv.y);
                    mma_h(acc[mg][nn], Ag[mg][0].z, Ag[mg][1].z, Ag[mg][0].w, Ag[mg][1].w,
                          Bv.z, Bv.w);
                }
            }
        }
        buf ^= 1;
    }

#pragma unroll
    for (int mg = 0; mg < 2; mg++) {
        const int row0 = m0 + wm + mg * 16 + g;
        const int row1 = row0 + 8;
#pragma unroll
        for (int nn = 0; nn < 8; nn++) {
            const int col = n0 + wn + nn * 8 + 2 * t;
            *(float2*)&C[(size_t)row0 * N + col] = make_float2(acc[mg][nn][0], acc[mg][nn][1]);
            *(float2*)&C[(size_t)row1 * N + col] = make_float2(acc[mg][nn][2], acc[mg][nn][3]);
        }
    }
}

// ---------------------------------------------------------------------------
// LayerNorm(q,k)*D^-0.25 + split (R15 verbatim)
// ---------------------------------------------------------------------------
__global__ __launch_bounds__(256) void ln_split_h_kernel(
    const float* __restrict__ qkv,
    const float* __restrict__ q_scale, const float* __restrict__ q_bias,
    const float* __restrict__ k_scale, const float* __restrict__ k_bias,
    uint32_t* __restrict__ q_h, uint32_t* __restrict__ k_h, uint32_t* __restrict__ v_h)
{
    const int wid  = (blockIdx.x * blockDim.x + threadIdx.x) >> 5;
    const int lane = threadIdx.x & 31;
    const int h = wid & (HEADS - 1);
    const int m = wid >> 4;
    const int b = m >> 11;
    const int l = m & (L_SEQ - 1);

    const float* row = qkv + (size_t)m * THREEC;
    const size_t tok = ((size_t)(b * HEADS + h)) * L_SEQ + l;
    const int d0 = 2 * lane, d1 = 2 * lane + 1;
    const int ppos = (lane & 16) | p16(lane & 15);

    {
        float x0 = row[h * HD + d0];
        float x1 = row[h * HD + d1];
        float s = x0 + x1;
#pragma unroll
        for (int o = 16; o > 0; o >>= 1) s += __shfl_xor_sync(0xffffffffu, s, o);
        float mu = s * (1.f / HD);
        float e0 = x0 - mu, e1 = x1 - mu;
        float vs = e0 * e0 + e1 * e1;
#pragma unroll
        for (int o = 16; o > 0; o >>= 1) vs += __shfl_xor_sync(0xffffffffu, vs, o);
        float rstd = rsqrtf(vs * (1.f / HD) + 1e-6f);
        float y0 = (e0 * rstd * q_scale[d0] + q_bias[d0]) * INV4;
        float y1 = (e1 * rstd * q_scale[d1] + q_bias[d1]) * INV4;
        q_h[tok * 32 + ppos] = pack_h2(y0, y1);
    }
    {
        float x0 = row[CDIM + h * HD + d0];
        float x1 = row[CDIM + h * HD + d1];
        float s = x0 + x1;
#pragma unroll
        for (int o = 16; o > 0; o >>= 1) s += __shfl_xor_sync(0xffffffffu, s, o);
        float mu = s * (1.f / HD);
        float e0 = x0 - mu, e1 = x1 - mu;
        float vs = e0 * e0 + e1 * e1;
#pragma unroll
        for (int o = 16; o > 0; o >>= 1) vs += __shfl_xor_sync(0xffffffffu, vs, o);
        float rstd = rsqrtf(vs * (1.f / HD) + 1e-6f);
        float y0 = (e0 * rstd * k_scale[d0] + k_bias[d0]) * INV4;
        float y1 = (e1 * rstd * k_scale[d1] + k_bias[d1]) * INV4;
        k_h[tok * 32 + ppos] = pack_h2(y0, y1);
    }
    v_h[tok * 32 + lane] = pack_h2(row[2 * CDIM + h * HD + d0],
                                   row[2 * CDIM + h * HD + d1]);
}

// ---------------------------------------------------------------------------
// fp16 flash attention, double-buffered cp.async K/V pipeline.
// Q resident [128][48]; K/V: 2 stages x [64][48] each.
// smem: (128 + 4*64) * 48 * 4 = 73,728 B -> 2 CTAs/SM.
// ---------------------------------------------------------------------------
#define GS 48
#define KV_STAGE (64 * GS)
#define ATTN_SMEM_BYTES ((128 * GS + 4 * KV_STAGE) * 4)

__global__ __launch_bounds__(256, 2) void attn_h2_kernel(
    const uint32_t* __restrict__ q_h, const uint32_t* __restrict__ k_h,
    const uint32_t* __restrict__ v_t, uint32_t* __restrict__ atth)
{
    extern __shared__ uint32_t us[];
    uint32_t* Qh = us;                       // [128][48]
    uint32_t* Kh = us + 128 * GS;            // [2][64][48]
    uint32_t* Vt = us + 128 * GS + 2 * KV_STAGE;  // [2][64][48]

    const int tid  = threadIdx.x;
    const int w    = tid >> 5;
    const int lane = tid & 31;
    const int g = lane >> 2;
    const int t = lane & 3;
    const int bh = blockIdx.y;
    const int q0 = blockIdx.x * 128;
    const int qr0 = w * 16;

    const uint32_t* Qp = q_h + (size_t)bh * L_SEQ * 32;
    const uint32_t* Kp = k_h + (size_t)bh * L_SEQ * 32;
    const uint32_t* Vp = v_t + (size_t)bh * 64 * (L_SEQ / 2);

    // copy slots: K tile 64 rows x 32 u32 = 512 uint4 -> 2/thread; same for V
    const int kr = tid >> 2;              // 0..63 row
    const int kc = (tid & 3) * 8;         // 0,8,16,24 (two uint4 at +0,+4)

    // Q tile once (synchronous; once per CTA)
#pragma unroll
    for (int i = 0; i < 4; i++) {
        int id = i * 256 + tid;
        int rr = id >> 3;
        int c4 = (id & 7) * 4;
        *(uint4*)&Qh[rr * GS + c4] = *(const uint4*)&Qp[(size_t)(q0 + rr) * 32 + c4];
    }

    // prologue: stage 0 K/V in flight
    cp16(&Kh[kr * GS + kc],     &Kp[(size_t)kr * 32 + kc]);
    cp16(&Kh[kr * GS + kc + 4], &Kp[(size_t)kr * 32 + kc + 4]);
    cp16(&Vt[kr * GS + kc],     &Vp[(size_t)kr * (L_SEQ / 2) + kc]);
    cp16(&Vt[kr * GS + kc + 4], &Vp[(size_t)kr * (L_SEQ / 2) + kc + 4]);
    cp_commit();

    float o[8][4];
#pragma unroll
    for (int nn = 0; nn < 8; nn++)
#pragma unroll
        for (int v = 0; v < 4; v++) o[nn][v] = 0.f;
    float mrow0 = -1e30f, mrow1 = -1e30f;
    float lrow0 = 0.f,    lrow1 = 0.f;

    int buf = 0;
    for (int kt = 0; kt < L_SEQ; kt += 64) {
        cp_wait0();
        __syncthreads();

        if (kt + 64 < L_SEQ) {
            const int nb = buf ^ 1;
            cp16(&Kh[nb * KV_STAGE + kr * GS + kc],
                 &Kp[(size_t)(kt + 64 + kr) * 32 + kc]);
            cp16(&Kh[nb * KV_STAGE + kr * GS + kc + 4],
                 &Kp[(size_t)(kt + 64 + kr) * 32 + kc + 4]);
            cp16(&Vt[nb * KV_STAGE + kr * GS + kc],
                 &Vp[(size_t)kr * (L_SEQ / 2) + ((kt + 64) >> 1) + kc]);
            cp16(&Vt[nb * KV_STAGE + kr * GS + kc + 4],
                 &Vp[(size_t)kr * (L_SEQ / 2) + ((kt + 64) >> 1) + kc + 4]);
            cp_commit();
        }

        const uint32_t* kh = &Kh[buf * KV_STAGE];
        const uint32_t* vt = &Vt[buf * KV_STAGE];

        // S = Q K^T (fp16)
        float s[8][4];
#pragma unroll
        for (int nn = 0; nn < 8; nn++)
#pragma unroll
            for (int v = 0; v < 4; v++) s[nn][v] = 0.f;

#pragma unroll
        for (int kp = 0; kp < 2; kp++) {
            uint4 Qg  = *(const uint4*)&Qh[(qr0 + g)     * GS + kp * 16 + 4 * t];
            uint4 Qg8 = *(const uint4*)&Qh[(qr0 + g + 8) * GS + kp * 16 + 4 * t];
#pragma unroll
            for (int nn = 0; nn < 8; nn++) {
                uint4 Kv = *(const uint4*)&kh[(nn * 8 + g) * GS + kp * 16 + 4 * t];
                mma_h(s[nn], Qg.x, Qg8.x, Qg.y, Qg8.y, Kv.x, Kv.y);
                mma_h(s[nn], Qg.z, Qg8.z, Qg.w, Qg8.w, Kv.z, Kv.w);
            }
        }

        // online softmax (rows g, g+8; quad reductions)
        float mx0 = -1e30f, mx1 = -1e30f;
#pragma unroll
        for (int nn = 0; nn < 8; nn++) {
            mx0 = fmaxf(mx0, fmaxf(s[nn][0], s[nn][1]));
            mx1 = fmaxf(mx1, fmaxf(s[nn][2], s[nn][3]));
        }
        mx0 = fmaxf(mx0, __shfl_xor_sync(0xffffffffu, mx0, 1));
        mx0 = fmaxf(mx0, __shfl_xor_sync(0xffffffffu, mx0, 2));
        mx1 = fmaxf(mx1, __shfl_xor_sync(0xffffffffu, mx1, 1));
        mx1 = fmaxf(mx1, __shfl_xor_sync(0xffffffffu, mx1, 2));

        float mn0 = fmaxf(mrow0, mx0);
        float mn1 = fmaxf(mrow1, mx1);
        float alpha0 = __expf(mrow0 - mn0);
        float alpha1 = __expf(mrow1 - mn1);
        mrow0 = mn0; mrow1 = mn1;

        float rs0 = 0.f, rs1 = 0.f;
#pragma unroll
        for (int nn = 0; nn < 8; nn++) {
            s[nn][0] = __expf(s[nn][0] - mn0);
            s[nn][1] = __expf(s[nn][1] - mn0);
            s[nn][2] = __expf(s[nn][2] - mn1);
            s[nn][3] = __expf(s[nn][3] - mn1);
            rs0 += s[nn][0] + s[nn][1];
            rs1 += s[nn][2] + s[nn][3];
        }
        rs0 += __shfl_xor_sync(0xffffffffu, rs0, 1);
        rs0 += __shfl_xor_sync(0xffffffffu, rs0, 2);
        rs1 += __shfl_xor_sync(0xffffffffu, rs1, 1);
        rs1 += __shfl_xor_sync(0xffffffffu, rs1, 2);
        lrow0 = lrow0 * alpha0 + rs0;
        lrow1 = lrow1 * alpha1 + rs1;

#pragma unroll
        for (int nn = 0; nn < 8; nn++) {
            o[nn][0] *= alpha0; o[nn][1] *= alpha0;
            o[nn][2] *= alpha1; o[nn][3] *= alpha1;
        }

        // O += P V : register-only P repack (validated ordering)
#pragma unroll
        for (int kp = 0; kp < 2; kp++) {
            uint32_t ae0 = pack_h2(s[4 * kp + 0][0], s[4 * kp + 0][1]);
            uint32_t ae1 = pack_h2(s[4 * kp + 0][2], s[4 * kp + 0][3]);
            uint32_t ae2 = pack_h2(s[4 * kp + 1][0], s[4 * kp + 1][1]);
            uint32_t ae3 = pack_h2(s[4 * kp + 1][2], s[4 * kp + 1][3]);
            uint32_t ao0 = pack_h2(s[4 * kp + 2][0], s[4 * kp + 2][1]);
            uint32_t ao1 = pack_h2(s[4 * kp + 2][2], s[4 * kp + 2][3]);
            uint32_t ao2 = pack_h2(s[4 * kp + 3][0], s[4 * kp + 3][1]);
            uint32_t ao3 = pack_h2(s[4 * kp + 3][2], s[4 * kp + 3][3]);
#pragma unroll
            for (int nn = 0; nn < 8; nn++) {
                uint4 Vv = *(const uint4*)&vt[(nn * 8 + g) * GS + kp * 16 + 4 * t];
                mma_h(o[nn], ae0, ae1, ae2, ae3, Vv.x, Vv.y);
                mma_h(o[nn], ao0, ao1, ao2, ao3, Vv.z, Vv.w);
            }
        }
        buf ^= 1;
    }

    // finalize + store half perm16 directly
    const int b_ = bh >> 4;
    const int h  = bh & (HEADS - 1);
    const float inv0 = 1.f / lrow0;
    const float inv1 = 1.f / lrow1;
    const int tok0 = b_ * L_SEQ + q0 + qr0 + g;
    const int tok1 = tok0 + 8;
#pragma unroll
    for (int nn = 0; nn < 8; nn++) {
        int pos = h * 32 + ((nn >> 2) << 4) + 4 * t + (nn & 3);
        atth[(size_t)tok0 * 512 + pos] = pack_h2(o[nn][0] * inv0, o[nn][1] * inv0);
        atth[(size_t)tok1 * 512 + pos] = pack_h2(o[nn][2] * inv1, o[nn][3] * inv1);
    }
}

// ---------------------------------------------------------------------------
// Host launch
// ---------------------------------------------------------------------------
extern "C" void kernel_launch(void* const* d_in, const int* in_sizes, int n_in,
                              void* d_out, int out_size)
{
    const float* x       = (const float*)d_in[0];
    const float* w_qkv   = (const float*)d_in[1];
    const float* w_out   = (const float*)d_in[2];
    const float* q_scale = (const float*)d_in[3];
    const float* q_bias  = (const float*)d_in[4];
    const float* k_scale = (const float*)d_in[5];
    const float* k_bias  = (const float*)d_in[6];
    float* out = (float*)d_out;

    void *p_qkv, *p_qh, *p_kh, *p_vh, *p_vt, *p_xh, *p_wh, *p_worh, *p_atth;
    cudaGetSymbolAddress(&p_qkv, g_qkv);
    cudaGetSymbolAddress(&p_qh, g_qh);
    cudaGetSymbolAddress(&p_kh, g_kh);
    cudaGetSymbolAddress(&p_vh, g_vh);
    cudaGetSymbolAddress(&p_vt, g_vt);
    cudaGetSymbolAddress(&p_xh, g_xh);
    cudaGetSymbolAddress(&p_wh, g_wh);
    cudaGetSymbolAddress(&p_worh, g_worh);
    cudaGetSymbolAddress(&p_atth, g_atth);

    // 0) prep
    cvt_perm_kernel<<<(MTOT * 256 + 255) / 256, 256>>>(x, (uint32_t*)p_xh, MTOT * 256);
    transpose_cvt_perm_kernel<<<dim3(THREEC / 32, CDIM / 32), 256>>>(
        w_qkv, (uint32_t*)p_wh, CDIM, THREEC);
    transpose_cvt_perm_kernel<<<dim3(CDIM / 32, CDIM / 32), 256>>>(
        w_out, (uint32_t*)p_worh, CDIM, CDIM);

    // 1) QKV projection
    cudaFuncSetAttribute(gemm_h_kernel, cudaFuncAttributeMaxDynamicSharedMemorySize,
                         GEMM_SMEM_BYTES);
    gemm_h_kernel<<<dim3(THREEC / 128, MTOT / 128), 256, GEMM_SMEM_BYTES>>>(
        (const uint32_t*)p_xh, (const uint32_t*)p_wh, (float*)p_qkv, MTOT, THREEC);

    // 2) QK LayerNorm + split
    ln_split_h_kernel<<<(MTOT * HEADS) / 8, 256>>>(
        (const float*)p_qkv, q_scale, q_bias, k_scale, k_bias,
        (uint32_t*)p_qh, (uint32_t*)p_kh, (uint32_t*)p_vh);

    // 2b) V transpose
    transpose_v_kernel<<<dim3(L_SEQ / 64, BATCH * HEADS), 256>>>(
        (const uint32_t*)p_vh, (uint32_t*)p_vt);

    // 3) Flash attention (cp.async K/V pipeline)
    cudaFuncSetAttribute(attn_h2_kernel, cudaFuncAttributeMaxDynamicSharedMemorySize,
                         ATTN_SMEM_BYTES);
    attn_h2_kernel<<<dim3(L_SEQ / 128, BATCH * HEADS), 256, ATTN_SMEM_BYTES>>>(
        (const uint32_t*)p_qh, (const uint32_t*)p_kh, (const uint32_t*)p_vt,
        (uint32_t*)p_atth);

    // 4) Output projection
    gemm_h_kernel<<<dim3(CDIM / 128, MTOT / 128), 256, GEMM_SMEM_BYTES>>>(
        (const uint32_t*)p_atth, (const uint32_t*)p_worh, out, MTOT, CDIM);
}

// round 17
// speedup vs baseline: 1.0601x; 1.0601x over previous
#include <cuda_runtime.h>
#include <cuda_fp16.h>
#include <cstdint>

// Problem constants
#define BATCH 2
#define L_SEQ 2048
#define CDIM  1024
#define HEADS 16
#define HD    64
#define MTOT  4096
#define THREEC 3072
#define INV4  0.3535533905932738f   // 64^-0.25

// ---------------------------------------------------------------------------
// Scratch (device globals; no allocation allowed)
// ---------------------------------------------------------------------------
__device__ __align__(16) uint32_t g_qh  [(size_t)MTOT * 512];     // q half perm16 [B,H,L]
__device__ __align__(16) uint32_t g_kh  [(size_t)MTOT * 512];     // k half perm16 [B,H,L]
__device__ __align__(16) uint32_t g_vh  [(size_t)MTOT * 512];     // v half natural [B,H,L][d2]
__device__ __align__(16) uint32_t g_vt  [(size_t)MTOT * 512];     // v^T half [B,H][d][key2 perm16]
__device__ __align__(16) uint32_t g_xh  [(size_t)MTOT * 512];     // x half perm16
__device__ __align__(16) uint32_t g_wh  [(size_t)THREEC * 512];   // w_qkv^T half perm16
__device__ __align__(16) uint32_t g_worh[(size_t)CDIM * 512];     // w_out^T half perm16
__device__ __align__(16) uint32_t g_atth[(size_t)MTOT * 512];     // attn out half perm16

// ---------------------------------------------------------------------------
// Helpers
// ---------------------------------------------------------------------------
__device__ __forceinline__ int p16(int c) { return ((c & 3) << 2) | (c >> 2); }

__device__ __forceinline__ uint32_t pack_h2(float a, float b) {
    __half2 h = __floats2half2_rn(a, b);     // low = a, high = b
    return *reinterpret_cast<uint32_t*>(&h);
}

__device__ __forceinline__ void mma_h(float* d,
                                      uint32_t a0, uint32_t a1, uint32_t a2, uint32_t a3,
                                      uint32_t b0, uint32_t b1) {
    asm volatile(
        "mma.sync.aligned.m16n8k16.row.col.f32.f16.f16.f32 "
        "{%0,%1,%2,%3}, {%4,%5,%6,%7}, {%8,%9}, {%0,%1,%2,%3};\n"
        : "+f"(d[0]), "+f"(d[1]), "+f"(d[2]), "+f"(d[3])
        : "r"(a0), "r"(a1), "r"(a2), "r"(a3), "r"(b0), "r"(b1));
}

__device__ __forceinline__ void cp16(void* smem, const void* gmem) {
    uint32_t s = (uint32_t)__cvta_generic_to_shared(smem);
    asm volatile("cp.async.ca.shared.global [%0], [%1], 16;" :: "r"(s), "l"(gmem));
}
__device__ __forceinline__ void cp_commit() { asm volatile("cp.async.commit_group;"); }
__device__ __forceinline__ void cp_wait0()  { asm volatile("cp.async.wait_group 0;"); }

// ---------------------------------------------------------------------------
// Prep: f32 [R][1024] -> half u32 [R][512] with perm16 along K (validated)
// ---------------------------------------------------------------------------
__global__ __launch_bounds__(256) void cvt_perm_kernel(
    const float* __restrict__ src, uint32_t* __restrict__ dst, int n_f4)
{
    int i = blockIdx.x * blockDim.x + threadIdx.x;
    if (i >= n_f4) return;
    float4 v = ((const float4*)src)[i];
    int row = i >> 8;
    int f4  = i & 255;
    int k2a = 2 * f4, k2b = 2 * f4 + 1;
    int base = row * 512;
    dst[base + (k2a & ~15) + p16(k2a & 15)] = pack_h2(v.x, v.y);
    dst[base + (k2b & ~15) + p16(k2b & 15)] = pack_h2(v.z, v.w);
}

// f32 [K][C] -> half u32 [C][K/2] (transposed) with perm16 along K (validated)
__global__ __launch_bounds__(256) void transpose_cvt_perm_kernel(
    const float* __restrict__ src, uint32_t* __restrict__ dst, int K, int C)
{
    __shared__ float tile[32][33];
    const int c0 = blockIdx.x * 32, k0 = blockIdx.y * 32;
    const int tx = threadIdx.x & 31;
    const int ty = threadIdx.x >> 5;
#pragma unroll
    for (int j = 0; j < 4; j++)
        tile[ty + j * 8][tx] = src[(size_t)(k0 + ty + j * 8) * C + c0 + tx];
    __syncthreads();
#pragma unroll
    for (int j = 0; j < 2; j++) {
        int k2l = ty + 8 * j;
        uint32_t h = pack_h2(tile[2 * k2l][tx], tile[2 * k2l + 1][tx]);
        dst[(size_t)(c0 + tx) * (K / 2) + (k0 >> 1) + p16(k2l)] = h;
    }
}

// ---------------------------------------------------------------------------
// V transpose: vh [bh][L][32 u32] -> vt [bh][64 d][L/2 u32] perm16 (validated)
// ---------------------------------------------------------------------------
__global__ __launch_bounds__(256) void transpose_v_kernel(
    const uint32_t* __restrict__ vh, uint32_t* __restrict__ vt)
{
    __shared__ uint32_t tile[64][33];
    const int bh = blockIdx.y;
    const int t0 = blockIdx.x * 64;
    const int tid = threadIdx.x;

    const uint32_t* src = vh + (size_t)bh * L_SEQ * 32 + (size_t)t0 * 32;
#pragma unroll
    for (int i = 0; i < 8; i++) {
        int idx = tid + i * 256;
        int tok = idx >> 5;
        int d2  = idx & 31;
        tile[tok][d2] = src[tok * 32 + d2];
    }
    __syncthreads();

    uint32_t* dst = vt + (size_t)bh * 64 * (L_SEQ / 2) + (t0 >> 1);
#pragma unroll
    for (int i = 0; i < 8; i++) {
        int idx = tid + i * 256;
        int d   = idx >> 5;
        int k2l = idx & 31;
        uint32_t w0 = tile[2 * k2l][d >> 1];
        uint32_t w1 = tile[2 * k2l + 1][d >> 1];
        uint32_t lo = (d & 1) ? (w0 >> 16) : (w0 & 0xFFFFu);
        uint32_t hi = (d & 1) ? (w1 & 0xFFFF0000u) : (w1 << 16);
        int pos = (k2l & 16) | p16(k2l & 15);
        dst[(size_t)d * (L_SEQ / 2) + pos] = lo | hi;
    }
}

// ---------------------------------------------------------------------------
// Common GEMM mainloop config (R14-validated)
// ---------------------------------------------------------------------------
#define GSG 48
#define STAGE_U32 (128 * GSG)
#define GEMM_SMEM_BYTES (4 * STAGE_U32 * 4)

// ---------------------------------------------------------------------------
// QKV GEMM with fused LayerNorm epilogue.
// M=4096 tokens, N=3072. Warp column block (64 cols) = one head of q/k/v.
// Epilogue: q/k -> LN(quad-shfl) * INV4 -> half perm16; v -> half natural.
// ---------------------------------------------------------------------------
__global__ __launch_bounds__(256, 2) void gemm_qkv_ln_kernel(
    const uint32_t* __restrict__ A, const uint32_t* __restrict__ Bt,
    const float* __restrict__ q_scale, const float* __restrict__ q_bias,
    const float* __restrict__ k_scale, const float* __restrict__ k_bias,
    uint32_t* __restrict__ q_h, uint32_t* __restrict__ k_h, uint32_t* __restrict__ v_h)
{
    extern __shared__ uint32_t us[];
    uint32_t* As = us;
    uint32_t* Bs = us + 2 * STAGE_U32;

    const int tid  = threadIdx.x;
    const int w    = tid >> 5;
    const int lane = tid & 31;
    const int g = lane >> 2;
    const int t = lane & 3;
    const int m0 = blockIdx.y * 128;
    const int n0 = blockIdx.x * 128;
    const int wm = (w & 3) * 32;
    const int wn = (w >> 2) * 64;
    const int K2 = 512;

    const int cp_r0 = tid >> 3;
    const int cp_c4 = (tid & 7) * 4;

    float acc[2][8][4];
#pragma unroll
    for (int mg = 0; mg < 2; mg++)
#pragma unroll
        for (int nn = 0; nn < 8; nn++)
#pragma unroll
            for (int v = 0; v < 4; v++) acc[mg][nn][v] = 0.f;

    {
#pragma unroll
        for (int i = 0; i < 4; i++) {
            int rr = cp_r0 + i * 32;
            cp16(&As[rr * GSG + cp_c4], &A[(size_t)(m0 + rr) * K2 + cp_c4]);
            cp16(&Bs[rr * GSG + cp_c4], &Bt[(size_t)(n0 + rr) * K2 + cp_c4]);
        }
        cp_commit();
    }

    int buf = 0;
    for (int k0 = 0; k0 < K2; k0 += 32) {
        cp_wait0();
        __syncthreads();

        if (k0 + 32 < K2) {
            const int nb = buf ^ 1;
#pragma unroll
            for (int i = 0; i < 4; i++) {
                int rr = cp_r0 + i * 32;
                cp16(&As[nb * STAGE_U32 + rr * GSG + cp_c4],
                     &A[(size_t)(m0 + rr) * K2 + k0 + 32 + cp_c4]);
                cp16(&Bs[nb * STAGE_U32 + rr * GSG + cp_c4],
                     &Bt[(size_t)(n0 + rr) * K2 + k0 + 32 + cp_c4]);
            }
            cp_commit();
        }

        const uint32_t* as = &As[buf * STAGE_U32];
        const uint32_t* bs = &Bs[buf * STAGE_U32];
#pragma unroll
        for (int kp = 0; kp < 2; kp++) {
            uint4 Ag[2][2];
#pragma unroll
            for (int mg = 0; mg < 2; mg++) {
                Ag[mg][0] = *(const uint4*)&as[(wm + mg * 16 + g)     * GSG + kp * 16 + 4 * t];
                Ag[mg][1] = *(const uint4*)&as[(wm + mg * 16 + g + 8) * GSG + kp * 16 + 4 * t];
            }
#pragma unroll
            for (int nn = 0; nn < 8; nn++) {
                uint4 Bv = *(const uint4*)&bs[(wn + nn * 8 + g) * GSG + kp * 16 + 4 * t];
#pragma unroll
                for (int mg = 0; mg < 2; mg++) {
                    mma_h(acc[mg][nn], Ag[mg][0].x, Ag[mg][1].x, Ag[mg][0].y, Ag[mg][1].y,
                          Bv.x, Bv.y);
                    mma_h(acc[mg][nn], Ag[mg][0].z, Ag[mg][1].z, Ag[mg][0].w, Ag[mg][1].w,
                          Bv.z, Bv.w);
                }
            }
        }
        buf ^= 1;
    }

    // ---- fused epilogue ----
    const int col0 = n0 + wn;             // multiple of 64
    const int type = col0 >> 10;          // 0=q, 1=k, 2=v
    const int h    = (col0 & 1023) >> 6;  // head

    if (type < 2) {
        const float* sc = (type == 0) ? q_scale : k_scale;
        const float* bi = (type == 0) ? q_bias  : k_bias;
        uint32_t*   dst = (type == 0) ? q_h     : k_h;
#pragma unroll
        for (int mg = 0; mg < 2; mg++) {
            // row sums (rows row0 = ..+g, row1 = row0+8)
            float s0 = 0.f, s1 = 0.f;
#pragma unroll
            for (int nn = 0; nn < 8; nn++) {
                s0 += acc[mg][nn][0] + acc[mg][nn][1];
                s1 += acc[mg][nn][2] + acc[mg][nn][3];
            }
            s0 += __shfl_xor_sync(0xffffffffu, s0, 1);
            s0 += __shfl_xor_sync(0xffffffffu, s0, 2);
            s1 += __shfl_xor_sync(0xffffffffu, s1, 1);
            s1 += __shfl_xor_sync(0xffffffffu, s1, 2);
            float mu0 = s0 * (1.f / HD);
            float mu1 = s1 * (1.f / HD);

            float v0 = 0.f, v1 = 0.f;
#pragma unroll
            for (int nn = 0; nn < 8; nn++) {
                float e0 = acc[mg][nn][0] - mu0, e1 = acc[mg][nn][1] - mu0;
                float e2 = acc[mg][nn][2] - mu1, e3 = acc[mg][nn][3] - mu1;
                v0 += e0 * e0 + e1 * e1;
                v1 += e2 * e2 + e3 * e3;
            }
            v0 += __shfl_xor_sync(0xffffffffu, v0, 1);
            v0 += __shfl_xor_sync(0xffffffffu, v0, 2);
            v1 += __shfl_xor_sync(0xffffffffu, v1, 1);
            v1 += __shfl_xor_sync(0xffffffffu, v1, 2);
            float rstd0 = rsqrtf(v0 * (1.f / HD) + 1e-6f);
            float rstd1 = rsqrtf(v1 * (1.f / HD) + 1e-6f);

            const int m_row0 = m0 + wm + mg * 16 + g;
            const int m_row1 = m_row0 + 8;
            const size_t tok0 = ((size_t)((m_row0 >> 11) * HEADS + h)) * L_SEQ + (m_row0 & 2047);
            const size_t tok1 = ((size_t)((m_row1 >> 11) * HEADS + h)) * L_SEQ + (m_row1 & 2047);
#pragma unroll
            for (int nn = 0; nn < 8; nn++) {
                int d0 = nn * 8 + 2 * t;
                int d1 = d0 + 1;
                float sc0 = sc[d0], sc1 = sc[d1];
                float bi0 = bi[d0], bi1 = bi[d1];
                float y00 = ((acc[mg][nn][0] - mu0) * rstd0 * sc0 + bi0) * INV4;
                float y01 = ((acc[mg][nn][1] - mu0) * rstd0 * sc1 + bi1) * INV4;
                float y10 = ((acc[mg][nn][2] - mu1) * rstd1 * sc0 + bi0) * INV4;
                float y11 = ((acc[mg][nn][3] - mu1) * rstd1 * sc1 + bi1) * INV4;
                int d2 = nn * 4 + t;
                int pos = (d2 & 16) | p16(d2 & 15);
                dst[tok0 * 32 + pos] = pack_h2(y00, y01);
                dst[tok1 * 32 + pos] = pack_h2(y10, y11);
            }
        }
    } else {
        // v: plain half pack, natural d2 layout
#pragma unroll
        for (int mg = 0; mg < 2; mg++) {
            const int m_row0 = m0 + wm + mg * 16 + g;
            const int m_row1 = m_row0 + 8;
            const size_t tok0 = ((size_t)((m_row0 >> 11) * HEADS + h)) * L_SEQ + (m_row0 & 2047);
            const size_t tok1 = ((size_t)((m_row1 >> 11) * HEADS + h)) * L_SEQ + (m_row1 & 2047);
#pragma unroll
            for (int nn = 0; nn < 8; nn++) {
                int d2 = nn * 4 + t;
                v_h[tok0 * 32 + d2] = pack_h2(acc[mg][nn][0], acc[mg][nn][1]);
                v_h[tok1 * 32 + d2] = pack_h2(acc[mg][nn][2], acc[mg][nn][3]);
            }
        }
    }
}

// ---------------------------------------------------------------------------
// fp16 GEMM, 2-stage cp.async double-buffered (R14 verbatim) — out-proj only.
// ---------------------------------------------------------------------------
__global__ __launch_bounds__(256, 2) void gemm_h_kernel(
    const uint32_t* __restrict__ A, const uint32_t* __restrict__ Bt,
    float* __restrict__ C, int M, int N)
{
    extern __shared__ uint32_t us[];
    uint32_t* As = us;
    uint32_t* Bs = us + 2 * STAGE_U32;

    const int tid  = threadIdx.x;
    const int w    = tid >> 5;
    const int lane = tid & 31;
    const int g = lane >> 2;
    const int t = lane & 3;
    const int m0 = blockIdx.y * 128;
    const int n0 = blockIdx.x * 128;
    const int wm = (w & 3) * 32;
    const int wn = (w >> 2) * 64;
    const int K2 = 512;

    const int cp_r0 = tid >> 3;
    const int cp_c4 = (tid & 7) * 4;

    float acc[2][8][4];
#pragma unroll
    for (int mg = 0; mg < 2; mg++)
#pragma unroll
        for (int nn = 0; nn < 8; nn++)
#pragma unroll
            for (int v = 0; v < 4; v++) acc[mg][nn][v] = 0.f;

    {
#pragma unroll
        for (int i = 0; i < 4; i++) {
            int rr = cp_r0 + i * 32;
            cp16(&As[rr * GSG + cp_c4], &A[(size_t)(m0 + rr) * K2 + cp_c4]);
            cp16(&Bs[rr * GSG + cp_c4], &Bt[(size_t)(n0 + rr) * K2 + cp_c4]);
        }
        cp_commit();
    }

    int buf = 0;
    for (int k0 = 0; k0 < K2; k0 += 32) {
        cp_wait0();
        __syncthreads();

        if (k0 + 32 < K2) {
            const int nb = buf ^ 1;
#pragma unroll
            for (int i = 0; i < 4; i++) {
                int rr = cp_r0 + i * 32;
                cp16(&As[nb * STAGE_U32 + rr * GSG + cp_c4],
                     &A[(size_t)(m0 + rr) * K2 + k0 + 32 + cp_c4]);
                cp16(&Bs[nb * STAGE_U32 + rr * GSG + cp_c4],
                     &Bt[(size_t)(n0 + rr) * K2 + k0 + 32 + cp_c4]);
            }
            cp_commit();
        }

        const uint32_t* as = &As[buf * STAGE_U32];
        const uint32_t* bs = &Bs[buf * STAGE_U32];
#pragma unroll
        for (int kp = 0; kp < 2; kp++) {
            uint4 Ag[2][2];
#pragma unroll
            for (int mg = 0; mg < 2; mg++) {
                Ag[mg][0] = *(const uint4*)&as[(wm + mg * 16 + g)     * GSG + kp * 16 + 4 * t];
                Ag[mg][1] = *(const uint4*)&as[(wm + mg * 16 + g + 8) * GSG + kp * 16 + 4 * t];
            }
#pragma unroll
            for (int nn = 0; nn < 8; nn++) {
                uint4 Bv = *(const uint4*)&bs[(wn + nn * 8 + g) * GSG + kp * 16 + 4 * t];
#pragma unroll
                for (int mg = 0; mg < 2; mg++) {
                    mma_h(acc[mg][nn], Ag[mg][0].x, Ag[mg][1].x, Ag[mg][0].y, Ag[mg][1].y,
                          Bv.x, Bv.y);
                    mma_h(acc[mg][nn], Ag[mg][0].z, Ag[mg][1].z, Ag[mg][0].w, Ag[mg][1].w,
                          Bv.z, Bv.w);
                }
            }
        }
        buf ^= 1;
    }

#pragma unroll
    for (int mg = 0; mg < 2; mg++) {
        const int row0 = m0 + wm + mg * 16 + g;
        const int row1 = row0 + 8;
#pragma unroll
        for (int nn = 0; nn < 8; nn++) {
            const int col = n0 + wn + nn * 8 + 2 * t;
            *(float2*)&C[(size_t)row0 * N + col] = make_float2(acc[mg][nn][0], acc[mg][nn][1]);
            *(float2*)&C[(size_t)row1 * N + col] = make_float2(acc[mg][nn][2], acc[mg][nn][3]);
        }
    }
}

// ---------------------------------------------------------------------------
// fp16 flash attention (R15 verbatim — best passing config)
// ---------------------------------------------------------------------------
#define GS 48
#define ATTN_SMEM_BYTES (256 * GS * 4)

__global__ __launch_bounds__(256, 2) void attn_h2_kernel(
    const uint32_t* __restrict__ q_h, const uint32_t* __restrict__ k_h,
    const uint32_t* __restrict__ v_t, uint32_t* __restrict__ atth)
{
    extern __shared__ uint32_t us[];
    uint32_t* Qh = us;                    // [128][GS]
    uint32_t* Kh = us + 128 * GS;         // [64][GS]
    uint32_t* Vt = us + 192 * GS;         // [64][GS]

    const int tid  = threadIdx.x;
    const int w    = tid >> 5;
    const int lane = tid & 31;
    const int g = lane >> 2;
    const int t = lane & 3;
    const int bh = blockIdx.y;
    const int q0 = blockIdx.x * 128;
    const int qr0 = w * 16;

    const uint32_t* Qp = q_h + (size_t)bh * L_SEQ * 32;
    const uint32_t* Kp = k_h + (size_t)bh * L_SEQ * 32;
    const uint32_t* Vp = v_t + (size_t)bh * 64 * (L_SEQ / 2);

#pragma unroll
    for (int i = 0; i < 4; i++) {
        int id = i * 256 + tid;
        int rr = id >> 3;
        int c4 = (id & 7) * 4;
        *(uint4*)&Qh[rr * GS + c4] = *(const uint4*)&Qp[(size_t)(q0 + rr) * 32 + c4];
    }

    float o[8][4];
#pragma unroll
    for (int nn = 0; nn < 8; nn++)
#pragma unroll
        for (int v = 0; v < 4; v++) o[nn][v] = 0.f;
    float mrow0 = -1e30f, mrow1 = -1e30f;
    float lrow0 = 0.f,    lrow1 = 0.f;

    for (int kt = 0; kt < L_SEQ; kt += 64) {
        __syncthreads();
#pragma unroll
        for (int i = 0; i < 2; i++) {
            int id = i * 256 + tid;
            int rr = id >> 3;
            int c4 = (id & 7) * 4;
            *(uint4*)&Kh[rr * GS + c4] = *(const uint4*)&Kp[(size_t)(kt + rr) * 32 + c4];
        }
#pragma unroll
        for (int i = 0; i < 2; i++) {
            int id = i * 256 + tid;
            int rr = id >> 3;
            int c4 = (id & 7) * 4;
            *(uint4*)&Vt[rr * GS + c4] =
                *(const uint4*)&Vp[(size_t)rr * (L_SEQ / 2) + (kt >> 1) + c4];
        }
        __syncthreads();

        float s[8][4];
#pragma unroll
        for (int nn = 0; nn < 8; nn++)
#pragma unroll
            for (int v = 0; v < 4; v++) s[nn][v] = 0.f;

#pragma unroll
        for (int kp = 0; kp < 2; kp++) {
            uint4 Qg  = *(const uint4*)&Qh[(qr0 + g)     * GS + kp * 16 + 4 * t];
            uint4 Qg8 = *(const uint4*)&Qh[(qr0 + g + 8) * GS + kp * 16 + 4 * t];
#pragma unroll
            for (int nn = 0; nn < 8; nn++) {
                uint4 Kv = *(const uint4*)&Kh[(nn * 8 + g) * GS + kp * 16 + 4 * t];
                mma_h(s[nn], Qg.x, Qg8.x, Qg.y, Qg8.y, Kv.x, Kv.y);
                mma_h(s[nn], Qg.z, Qg8.z, Qg.w, Qg8.w, Kv.z, Kv.w);
            }
        }

        float mx0 = -1e30f, mx1 = -1e30f;
#pragma unroll
        for (int nn = 0; nn < 8; nn++) {
            mx0 = fmaxf(mx0, fmaxf(s[nn][0], s[nn][1]));
            mx1 = fmaxf(mx1, fmaxf(s[nn][2], s[nn][3]));
        }
        mx0 = fmaxf(mx0, __shfl_xor_sync(0xffffffffu, mx0, 1));
        mx0 = fmaxf(mx0, __shfl_xor_sync(0xffffffffu, mx0, 2));
        mx1 = fmaxf(mx1, __shfl_xor_sync(0xffffffffu, mx1, 1));
        mx1 = fmaxf(mx1, __shfl_xor_sync(0xffffffffu, mx1, 2));

        float mn0 = fmaxf(mrow0, mx0);
        float mn1 = fmaxf(mrow1, mx1);
        float alpha0 = __expf(mrow0 - mn0);
        float alpha1 = __expf(mrow1 - mn1);
        mrow0 = mn0; mrow1 = mn1;

        float rs0 = 0.f, rs1 = 0.f;
#pragma unroll
        for (int nn = 0; nn < 8; nn++) {
            s[nn][0] = __expf(s[nn][0] - mn0);
            s[nn][1] = __expf(s[nn][1] - mn0);
            s[nn][2] = __expf(s[nn][2] - mn1);
            s[nn][3] = __expf(s[nn][3] - mn1);
            rs0 += s[nn][0] + s[nn][1];
            rs1 += s[nn][2] + s[nn][3];
        }
        rs0 += __shfl_xor_sync(0xffffffffu, rs0, 1);
        rs0 += __shfl_xor_sync(0xffffffffu, rs0, 2);
        rs1 += __shfl_xor_sync(0xffffffffu, rs1, 1);
        rs1 += __shfl_xor_sync(0xffffffffu, rs1, 2);
        lrow0 = lrow0 * alpha0 + rs0;
        lrow1 = lrow1 * alpha1 + rs1;

#pragma unroll
        for (int nn = 0; nn < 8; nn++) {
            o[nn][0] *= alpha0; o[nn][1] *= alpha0;
            o[nn][2] *= alpha1; o[nn][3] *= alpha1;
        }

#pragma unroll
        for (int kp = 0; kp < 2; kp++) {
            uint32_t ae0 = pack_h2(s[4 * kp + 0][0], s[4 * kp + 0][1]);
            uint32_t ae1 = pack_h2(s[4 * kp + 0][2], s[4 * kp + 0][3]);
            uint32_t ae2 = pack_h2(s[4 * kp + 1][0], s[4 * kp + 1][1]);
            uint32_t ae3 = pack_h2(s[4 * kp + 1][2], s[4 * kp + 1][3]);
            uint32_t ao0 = pack_h2(s[4 * kp + 2][0], s[4 * kp + 2][1]);
            uint32_t ao1 = pack_h2(s[4 * kp + 2][2], s[4 * kp + 2][3]);
            uint32_t ao2 = pack_h2(s[4 * kp + 3][0], s[4 * kp + 3][1]);
            uint32_t ao3 = pack_h2(s[4 * kp + 3][2], s[4 * kp + 3][3]);
#pragma unroll
            for (int nn = 0; nn < 8; nn++) {
                uint4 Vv = *(const uint4*)&Vt[(nn * 8 + g) * GS + kp * 16 + 4 * t];
                mma_h(o[nn], ae0, ae1, ae2, ae3, Vv.x, Vv.y);
                mma_h(o[nn], ao0, ao1, ao2, ao3, Vv.z, Vv.w);
            }
        }
    }

    const int b_ = bh >> 4;
    const int h  = bh & (HEADS - 1);
    const float inv0 = 1.f / lrow0;
    const float inv1 = 1.f / lrow1;
    const int tok0 = b_ * L_SEQ + q0 + qr0 + g;
    const int tok1 = tok0 + 8;
#pragma unroll
    for (int nn = 0; nn < 8; nn++) {
        int pos = h * 32 + ((nn >> 2) << 4) + 4 * t + (nn & 3);
        atth[(size_t)tok0 * 512 + pos] = pack_h2(o[nn][0] * inv0, o[nn][1] * inv0);
        atth[(size_t)tok1 * 512 + pos] = pack_h2(o[nn][2] * inv1, o[nn][3] * inv1);
    }
}

// ---------------------------------------------------------------------------
// Host launch
// ---------------------------------------------------------------------------
extern "C" void kernel_launch(void* const* d_in, const int* in_sizes, int n_in,
                              void* d_out, int out_size)
{
    const float* x       = (const float*)d_in[0];
    const float* w_qkv   = (const float*)d_in[1];
    const float* w_out   = (const float*)d_in[2];
    const float* q_scale = (const float*)d_in[3];
    const float* q_bias  = (const float*)d_in[4];
    const float* k_scale = (const float*)d_in[5];
    const float* k_bias  = (const float*)d_in[6];
    float* out = (float*)d_out;

    void *p_qh, *p_kh, *p_vh, *p_vt, *p_xh, *p_wh, *p_worh, *p_atth;
    cudaGetSymbolAddress(&p_qh, g_qh);
    cudaGetSymbolAddress(&p_kh, g_kh);
    cudaGetSymbolAddress(&p_vh, g_vh);
    cudaGetSymbolAddress(&p_vt, g_vt);
    cudaGetSymbolAddress(&p_xh, g_xh);
    cudaGetSymbolAddress(&p_wh, g_wh);
    cudaGetSymbolAddress(&p_worh, g_worh);
    cudaGetSymbolAddress(&p_atth, g_atth);

    // 0) prep
    cvt_perm_kernel<<<(MTOT * 256 + 255) / 256, 256>>>(x, (uint32_t*)p_xh, MTOT * 256);
    transpose_cvt_perm_kernel<<<dim3(THREEC / 32, CDIM / 32), 256>>>(
        w_qkv, (uint32_t*)p_wh, CDIM, THREEC);
    transpose_cvt_perm_kernel<<<dim3(CDIM / 32, CDIM / 32), 256>>>(
        w_out, (uint32_t*)p_worh, CDIM, CDIM);

    // 1) QKV projection + fused LayerNorm/split
    cudaFuncSetAttribute(gemm_qkv_ln_kernel, cudaFuncAttributeMaxDynamicSharedMemorySize,
                         GEMM_SMEM_BYTES);
    gemm_qkv_ln_kernel<<<dim3(THREEC / 128, MTOT / 128), 256, GEMM_SMEM_BYTES>>>(
        (const uint32_t*)p_xh, (const uint32_t*)p_wh,
        q_scale, q_bias, k_scale, k_bias,
        (uint32_t*)p_qh, (uint32_t*)p_kh, (uint32_t*)p_vh);

    // 2) V transpose
    transpose_v_kernel<<<dim3(L_SEQ / 64, BATCH * HEADS), 256>>>(
        (const uint32_t*)p_vh, (uint32_t*)p_vt);

    // 3) Flash attention (R15 config)
    cudaFuncSetAttribute(attn_h2_kernel, cudaFuncAttributeMaxDynamicSharedMemorySize,
                         ATTN_SMEM_BYTES);
    attn_h2_kernel<<<dim3(L_SEQ / 128, BATCH * HEADS), 256, ATTN_SMEM_BYTES>>>(
        (const uint32_t*)p_qh, (const uint32_t*)p_kh, (const uint32_t*)p_vt,
        (uint32_t*)p_atth);

    // 4) Output projection
    cudaFuncSetAttribute(gemm_h_kernel, cudaFuncAttributeMaxDynamicSharedMemorySize,
                         GEMM_SMEM_BYTES);
    gemm_h_kernel<<<dim3(CDIM / 128, MTOT / 128), 256, GEMM_SMEM_BYTES>>>(
        (const uint32_t*)p_atth, (const uint32_t*)p_worh, out, MTOT, CDIM);
}